// round 13
// baseline (speedup 1.0000x reference)
#include <cuda_runtime.h>
#include <math.h>

#define NN 10000
#define NSLICE 28
#define NB 140
#define NT 1024
#define OUTB 2048              // outputs per chunk (2 per thread)
#define MAXR 121               // max table rows any block needs
#define TW2 200                // u16 row width (even)
#define TABW (199 * 100)       // u32 words per global table copy = 19900
#define AWORDS (MAXR * 100)    // u32 words per smem copy = 12100
#define DB (AWORDS * 4)        // byte offset of smem copy B = 48400
#define SLIST_OFF (2 * DB)     // 96800, 16B aligned
#define SLIST_MAX 512
#define SMEM_BYTES (SLIST_OFF + SLIST_MAX * 4)
#define QSCALE 448.0f
#define K1B 16                 // tiny k_prep grid

__device__ unsigned g_tabA[TABW];        // quantized u16-pair table, copy A
__device__ unsigned g_tabB[TABW];        // one-u16-shifted copy B
__device__ float g_A[NN];                // A[di*100+j1] = sum_j2 sqrt(di^2+(j1-j2)^2)
__device__ int   g_list[NN];             // (i2+99)*200 + (j2+99)
__device__ int   g_nlist;
__device__ float g_pT[NSLICE * 10240];
__device__ float g_pS[NSLICE * 10240];
__device__ int   g_done;

__device__ __forceinline__ float sqrt_fast(float x) {
    float r; asm("sqrt.approx.f32 %0, %1;" : "=f"(r) : "f"(x)); return r;
}

// quantized distance at flat u16 index t of the 199x200 table
__device__ __forceinline__ unsigned qdist(int t) {
    int a = t / TW2;
    int c = t - a * TW2;
    int dx = a - 99, dy = c - 99;
    return __float2uint_rn(sqrt_fast((float)(dx * dx + dy * dy)) * QSCALE);
}

__device__ __forceinline__ float wscan(float x, int lane) {
    #pragma unroll
    for (int d = 1; d < 32; d <<= 1) {
        float v = __shfl_up_sync(0xffffffffu, x, d);
        if (lane >= d) x += v;
    }
    return x;
}

// ---------------------------------------------------------------------------
// K1 (16 blocks): bid0 = compaction + g_done reset; bid1-4 = A-rows (25 rows
// each, one warp per row); bid5-15 = grid-stride table gen.
// ---------------------------------------------------------------------------
__global__ __launch_bounds__(NT, 1) void k_prep(const float* __restrict__ gt) {
    const int bid = blockIdx.x;
    const int tid = threadIdx.x;
    const int warp = tid >> 5, lane = tid & 31;

    if (bid == 0) {
        // fully parallel deterministic compaction of py = (gt >= 0.5)
        __shared__ int swtot[32];
        __shared__ int swoff[32];
        float vv[10];
        const int o_base = warp * 320 + lane;   // warp owns [320w, 320w+320)
        #pragma unroll
        for (int it = 0; it < 10; ++it) {
            int o = o_base + it * 32;
            vv[it] = (o < NN) ? gt[o] : 0.0f;
        }
        if (tid == 0) g_done = 0;
        unsigned bal[10];
        #pragma unroll
        for (int it = 0; it < 10; ++it) {
            int o = o_base + it * 32;
            bool p = (o < NN) && (vv[it] >= 0.5f);
            bal[it] = __ballot_sync(0xffffffffu, p);
        }
        int pre[10]; int run = 0;
        #pragma unroll
        for (int it = 0; it < 10; ++it) { pre[it] = run; run += __popc(bal[it]); }
        if (lane == 0) swtot[warp] = run;
        __syncthreads();
        if (warp == 0) {
            int t = swtot[lane];
            int incl = t;
            #pragma unroll
            for (int d = 1; d < 32; d <<= 1) {
                int v = __shfl_up_sync(0xffffffffu, incl, d);
                if (lane >= d) incl += v;
            }
            swoff[lane] = incl - t;
            if (lane == 31) g_nlist = incl;
        }
        __syncthreads();
        int base = swoff[warp];
        #pragma unroll
        for (int it = 0; it < 10; ++it) {
            unsigned b = bal[it];
            if ((b >> lane) & 1u) {
                int o = o_base + it * 32;
                int pos = base + pre[it] + __popc(b & ((1u << lane) - 1u));
                int i2 = o / 100, j2 = o - i2 * 100;
                g_list[pos] = (i2 + 99) * TW2 + (j2 + 99);
            }
        }
    } else if (bid <= 4) {
        // A-rows: one warp per row, 25 rows per block.
        __shared__ float sp[25 * 100];
        if (warp < 25) {
            int di = (bid - 1) * 25 + warp;
            float fd2 = (float)(di * di);
            int d0 = lane, d1 = lane + 32, d2 = lane + 64, d3 = lane + 96;
            float v0 = sqrtf(fd2 + (float)(d0 * d0));
            float v1 = sqrtf(fd2 + (float)(d1 * d1));
            float v2 = sqrtf(fd2 + (float)(d2 * d2));
            float v3 = (d3 < 100) ? sqrtf(fd2 + (float)(d3 * d3)) : 0.f;
            float s0 = wscan((d0 >= 1) ? v0 : 0.f, lane);
            float t0 = __shfl_sync(0xffffffffu, s0, 31);
            float s1 = wscan(v1, lane);
            float t1 = t0 + __shfl_sync(0xffffffffu, s1, 31);
            float s2 = wscan(v2, lane);
            float t2 = t1 + __shfl_sync(0xffffffffu, s2, 31);
            float s3 = wscan(v3, lane);
            float* row = sp + warp * 100;
            row[d0] = s0;
            row[d1] = s1 + t0;
            row[d2] = s2 + t1;
            if (d3 < 100) row[d3] = s3 + t2;
            __syncwarp();
            float fdi = (float)di;
            g_A[di * 100 + d0] = fdi + row[d0] + row[99 - d0];
            g_A[di * 100 + d1] = fdi + row[d1] + row[99 - d1];
            g_A[di * 100 + d2] = fdi + row[d2] + row[99 - d2];
            if (d3 < 100) g_A[di * 100 + d3] = fdi + row[d3] + row[99 - d3];
        }
    } else {
        // table gen: 2*19900 words over 11 blocks, grid-stride
        for (int idx = (bid - 5) * NT + tid; idx < 2 * TABW; idx += 11 * NT) {
            if (idx < TABW) {
                int t0 = 2 * idx;
                g_tabA[idx] = qdist(t0) | (qdist(t0 + 1) << 16);
            } else {
                int w = idx - TABW;
                int t0 = 2 * w + 1;
                int t1 = (t0 + 1 < 2 * TABW) ? (t0 + 1) : t0;
                g_tabB[w] = qdist(t0) | (qdist(t1) << 16);
            }
        }
    }
}

// ---------------------------------------------------------------------------
// K2: stage table window, sparse DP2A accumulate, S partials, and the final
//     reduction in the LAST-finishing block (deterministic fixed-order sums).
// ---------------------------------------------------------------------------
__global__ __launch_bounds__(NT, 1) void k_main(const float* __restrict__ prob,
                                                float* __restrict__ out) {
    extern __shared__ unsigned char smraw[];
    unsigned* wA = (unsigned*)smraw;
    unsigned* wB = (unsigned*)(smraw + DB);
    int* slist = (int*)(smraw + SLIST_OFF);

    const int bid = blockIdx.x;
    const int tid = threadIdx.x;
    const int warp = tid >> 5, lane = tid & 31;

    const int chunk = bid / NSLICE;
    const int s = bid - chunk * NSLICE;
    const int o0 = chunk * OUTB;
    int i1hi = (o0 + OUTB - 1) / 100; if (i1hi > 99) i1hi = 99;
    const int i1lo = o0 / 100;
    const int rlo = 99 - i1hi;
    const int nrows = 100 + (i1hi - i1lo);
    const int nW = nrows * 100;

    // stage table window from L2 into smem
    {
        const int4* srcA = (const int4*)(g_tabA + rlo * 100);
        const int4* srcB = (const int4*)(g_tabB + rlo * 100);
        int4* dA = (int4*)wA;
        int4* dB = (int4*)wB;
        int nv = nW >> 2;
        for (int k2 = tid; k2 < nv; k2 += NT) {
            dA[k2] = srcA[k2];
            dB[k2] = srcB[k2];
        }
    }

    int n = g_nlist;
    int e0 = (s * n) / NSLICE;
    int e1 = ((s + 1) * n) / NSLICE;
    int cnt = e1 - e0;
    int badj = rlo * TW2 + 1;
    for (int k = tid; k < cnt; k += NT) {
        int F = g_list[e0 + k] - badj;
        int p = F & 1;
        slist[k] = 2 * (F - p) + p * DB;
    }
    __syncthreads();

    int oe = o0 + 2 * tid;
    bool valid = (oe < NN);
    int oc = valid ? oe : (NN - 2);
    int i1 = oc / 100;
    int j1 = oc - i1 * 100;
    int qq = j1 >> 1;

    unsigned baseA;
    asm("{ .reg .u64 t; cvta.to.shared.u64 t, %1; cvt.u32.u64 %0, t; }"
        : "=r"(baseA) : "l"(smraw));
    unsigned tb = baseA - 400u * (unsigned)i1 - 4u * (unsigned)qq;

    unsigned aE0 = 0, aE1 = 0, aO0 = 0, aO1 = 0;
    int k = 0;
    int n8 = cnt & ~7;
    for (; k < n8; k += 8) {
        int4 ea = *(const int4*)(slist + k);
        int4 eb = *(const int4*)(slist + k + 4);
        unsigned w0, w1, w2, w3, w4, w5, w6, w7;
        asm("ld.shared.u32 %0,[%1];" : "=r"(w0) : "r"(tb + (unsigned)ea.x));
        asm("ld.shared.u32 %0,[%1];" : "=r"(w1) : "r"(tb + (unsigned)ea.y));
        asm("ld.shared.u32 %0,[%1];" : "=r"(w2) : "r"(tb + (unsigned)ea.z));
        asm("ld.shared.u32 %0,[%1];" : "=r"(w3) : "r"(tb + (unsigned)ea.w));
        asm("ld.shared.u32 %0,[%1];" : "=r"(w4) : "r"(tb + (unsigned)eb.x));
        asm("ld.shared.u32 %0,[%1];" : "=r"(w5) : "r"(tb + (unsigned)eb.y));
        asm("ld.shared.u32 %0,[%1];" : "=r"(w6) : "r"(tb + (unsigned)eb.z));
        asm("ld.shared.u32 %0,[%1];" : "=r"(w7) : "r"(tb + (unsigned)eb.w));
        aE0 = __dp2a_lo(w0, 0x0100u, aE0); aO0 = __dp2a_lo(w0, 0x0001u, aO0);
        aE1 = __dp2a_lo(w1, 0x0100u, aE1); aO1 = __dp2a_lo(w1, 0x0001u, aO1);
        aE0 = __dp2a_lo(w2, 0x0100u, aE0); aO0 = __dp2a_lo(w2, 0x0001u, aO0);
        aE1 = __dp2a_lo(w3, 0x0100u, aE1); aO1 = __dp2a_lo(w3, 0x0001u, aO1);
        aE0 = __dp2a_lo(w4, 0x0100u, aE0); aO0 = __dp2a_lo(w4, 0x0001u, aO0);
        aE1 = __dp2a_lo(w5, 0x0100u, aE1); aO1 = __dp2a_lo(w5, 0x0001u, aO1);
        aE0 = __dp2a_lo(w6, 0x0100u, aE0); aO0 = __dp2a_lo(w6, 0x0001u, aO0);
        aE1 = __dp2a_lo(w7, 0x0100u, aE1); aO1 = __dp2a_lo(w7, 0x0001u, aO1);
    }
    for (; k < cnt; ++k) {
        unsigned w0;
        asm("ld.shared.u32 %0,[%1];" : "=r"(w0) : "r"(tb + (unsigned)slist[k]));
        aE0 = __dp2a_lo(w0, 0x0100u, aE0);
        aO0 = __dp2a_lo(w0, 0x0001u, aO0);
    }
    float Te = __uint2float_rn(aE0 + aE1) * (1.0f / QSCALE);
    float To = __uint2float_rn(aO0 + aO1) * (1.0f / QSCALE);

    // slice partial of the (input-independent) rowsum S for both outputs
    int i2a = (100 * s) / NSLICE;
    int i2b = (100 * (s + 1)) / NSLICE;
    float sve = 0.f, svo = 0.f;
    const float2* A2 = (const float2*)g_A;
    for (int i2 = i2a; i2 < i2b; ++i2) {
        int di = i1 - i2; if (di < 0) di = -di;
        float2 av = A2[di * 50 + qq];
        sve += av.x; svo += av.y;
    }

    if (valid) {
        *(float2*)&g_pT[s * 10240 + oe] = make_float2(Te, To);
        *(float2*)&g_pS[s * 10240 + oe] = make_float2(sve, svo);
    }

    // ---- last-finishing block performs the final reduction ----
    __shared__ int lastFlag;
    __threadfence();
    __syncthreads();
    if (tid == 0) {
        int fin = atomicAdd(&g_done, 1);
        lastFlag = (fin == NB - 1);
    }
    __syncthreads();
    if (lastFlag) {
        __threadfence();               // acquire: all partials visible
        __shared__ float wsum[32];
        float ls = 0.f;
        for (int o = tid; o < NN; o += NT) {
            float T = 0.f, S = 0.f;
            #pragma unroll
            for (int q2 = 0; q2 < NSLICE; ++q2) {
                T += g_pT[q2 * 10240 + o];
                S += g_pS[q2 * 10240 + o];
            }
            float px = (prob[o] >= 0.5f) ? 1.0f : 0.0f;
            ls += fabsf(px * S - T);
        }
        #pragma unroll
        for (int off = 16; off; off >>= 1)
            ls += __shfl_down_sync(0xffffffffu, ls, off);
        if (lane == 0) wsum[warp] = ls;
        __syncthreads();
        if (tid == 0) {
            float tt = 0.f;
            #pragma unroll
            for (int w = 0; w < 32; ++w) tt += wsum[w];
            out[0] = tt * (1.0f / ((float)NN * (float)NN));
        }
    }
}

extern "C" void kernel_launch(void* const* d_in, const int* in_sizes, int n_in,
                              void* d_out, int out_size) {
    const float* prob = (const float*)d_in[0];
    const float* gt   = (const float*)d_in[1];
    float* out = (float*)d_out;

    cudaFuncSetAttribute(k_main, cudaFuncAttributeMaxDynamicSharedMemorySize, SMEM_BYTES);
    k_prep<<<K1B, NT>>>(gt);
    k_main<<<NB, NT, SMEM_BYTES>>>(prob, out);
}

// round 14
// speedup vs baseline: 1.3924x; 1.3924x over previous
#include <cuda_runtime.h>
#include <math.h>

#define NN 10000
#define NSLICE 28
#define NCHUNK 5
#define NB 140
#define NT 1024
#define OUTB 2048              // outputs per chunk (2 per thread)
#define MAXR 121               // max table rows any block needs
#define TW2 200                // u16 row width (even)
#define TABW (199 * 100)       // u32 words per table copy = 19900
#define AWORDS (MAXR * 100)    // u32 words per smem copy = 12100
#define DB (AWORDS * 4)        // byte offset of smem copy B = 48400
#define SLIST_OFF (2 * DB)     // 96800, 16B aligned
#define SLIST_MAX 512
#define SMEM_BYTES (SLIST_OFF + SLIST_MAX * 4)
#define QSCALE 448.0

// ---------------------------------------------------------------------------
// Compile-time tables: quantized distance table (copies A and B) + A-row
// prefix table. All generated by constexpr Newton sqrt (double precision).
// ---------------------------------------------------------------------------
constexpr double csqrt(double x) {
    if (x <= 0.0) return 0.0;
    double r = 1.0;
    while (r * r < x) r *= 2.0;
    for (int i = 0; i < 8; ++i) r = 0.5 * (r + x / r);
    return r;
}

struct alignas(16) Tables {
    unsigned tA[TABW];
    unsigned tB[TABW];
    float A[NN];
};

constexpr Tables make_tables() {
    Tables T{};
    unsigned short v[2 * TABW] = {};
    for (int t = 0; t < 2 * TABW; ++t) {
        int a = t / TW2, c = t - a * TW2;
        double dx = (double)(a - 99), dy = (double)(c - 99);
        double s = csqrt(dx * dx + dy * dy);
        v[t] = (unsigned short)(s * QSCALE + 0.5);
    }
    for (int w = 0; w < TABW; ++w) {
        T.tA[w] = (unsigned)v[2 * w] | ((unsigned)v[2 * w + 1] << 16);
        int t1 = (2 * w + 2 < 2 * TABW) ? (2 * w + 2) : (2 * w + 1);
        T.tB[w] = (unsigned)v[2 * w + 1] | ((unsigned)v[t1] << 16);
    }
    for (int di = 0; di < 100; ++di) {
        double pref[100] = {};
        double run = 0.0;
        for (int d = 1; d < 100; ++d) {
            run += csqrt((double)(di * di + d * d));
            pref[d] = run;
        }
        for (int j = 0; j < 100; ++j)
            T.A[di * 100 + j] = (float)((double)di + pref[j] + pref[99 - j]);
    }
    return T;
}

__device__ const Tables c_tab = make_tables();

__device__ float g_pT[NSLICE * 10240];
__device__ float g_pS[NSLICE * 10240];
__device__ float g_cs[NCHUNK];
__device__ int   g_dc[NCHUNK];   // per-chunk arrival counters (zero-init)
__device__ int   g_done2;        // chunk-scalar counter (zero-init)

// ---------------------------------------------------------------------------
// Single kernel: per-block compaction + staging + DP2A accumulate + S
// partials + distributed last-arriver reduction. No grid barriers, no spins.
// ---------------------------------------------------------------------------
__global__ __launch_bounds__(NT, 1) void k_all(const float* __restrict__ prob,
                                               const float* __restrict__ gt,
                                               float* __restrict__ out) {
    extern __shared__ unsigned char smraw[];
    unsigned* wA = (unsigned*)smraw;
    unsigned* wB = (unsigned*)(smraw + DB);
    int* slist = (int*)(smraw + SLIST_OFF);

    __shared__ int swtot[32];
    __shared__ int swoff[32];
    __shared__ int sh_n;
    __shared__ int lastFlag;
    __shared__ float wsum[32];

    const int bid = blockIdx.x;
    const int tid = threadIdx.x;
    const int warp = tid >> 5, lane = tid & 31;

    const int chunk = bid / NSLICE;
    const int s = bid - chunk * NSLICE;
    const int o0 = chunk * OUTB;
    int i1hi = (o0 + OUTB - 1) / 100; if (i1hi > 99) i1hi = 99;
    const int i1lo = o0 / 100;
    const int rlo = 99 - i1hi;
    const int nrows = 100 + (i1hi - i1lo);
    const int nW = nrows * 100;
    const int badj = rlo * TW2 + 1;

    // ---- issue gt loads first (MLP=10); latency hides under staging ----
    float vv[10];
    const int o_base = warp * 320 + lane;   // warp owns [320w, 320w+320)
    #pragma unroll
    for (int it = 0; it < 10; ++it) {
        int o = o_base + it * 32;
        vv[it] = (o < NN) ? gt[o] : 0.0f;
    }
    // warm L2 with this chunk's prob lines (used by the tail reduce)
    if (tid < 64) {
        const char* p = (const char*)(prob + chunk * OUTB) + tid * 128;
        asm volatile("prefetch.global.L2 [%0];" :: "l"(p));
    }

    // ---- stage table window from L2 (static const data) into smem ----
    {
        const int4* srcA = (const int4*)(c_tab.tA + rlo * 100);
        const int4* srcB = (const int4*)(c_tab.tB + rlo * 100);
        int4* dA = (int4*)wA;
        int4* dB = (int4*)wB;
        int nv = nW >> 2;
        for (int k2 = tid; k2 < nv; k2 += NT) {
            dA[k2] = srcA[k2];
            dB[k2] = srcB[k2];
        }
    }

    // ---- per-block deterministic compaction of py = (gt >= 0.5) ----
    unsigned bal[10];
    #pragma unroll
    for (int it = 0; it < 10; ++it) {
        int o = o_base + it * 32;
        bool p = (o < NN) && (vv[it] >= 0.5f);
        bal[it] = __ballot_sync(0xffffffffu, p);
    }
    int pre[10]; int run = 0;
    #pragma unroll
    for (int it = 0; it < 10; ++it) { pre[it] = run; run += __popc(bal[it]); }
    if (lane == 0) swtot[warp] = run;
    __syncthreads();
    if (warp == 0) {
        int t = swtot[lane];
        int incl = t;
        #pragma unroll
        for (int d = 1; d < 32; d <<= 1) {
            int v = __shfl_up_sync(0xffffffffu, incl, d);
            if (lane >= d) incl += v;
        }
        swoff[lane] = incl - t;
        if (lane == 31) sh_n = incl;
    }
    __syncthreads();
    const int n = sh_n;
    const int e0 = (s * n) / NSLICE;
    const int e1 = ((s + 1) * n) / NSLICE;
    const int cnt = e1 - e0;
    {
        int base = swoff[warp];
        #pragma unroll
        for (int it = 0; it < 10; ++it) {
            unsigned b = bal[it];
            if ((b >> lane) & 1u) {
                int pos = base + pre[it] + __popc(b & ((1u << lane) - 1u));
                if (pos >= e0 && pos < e1) {
                    int o = o_base + it * 32;
                    int i2 = o / 100, j2 = o - i2 * 100;
                    int F = (i2 + 99) * TW2 + (j2 + 99) - badj;
                    int p2 = F & 1;
                    slist[pos - e0] = 2 * (F - p2) + p2 * DB;
                }
            }
        }
    }
    __syncthreads();

    // ---- main sparse DP2A accumulate (2 outputs per thread) ----
    int oe = o0 + 2 * tid;
    bool valid = (oe < NN);
    int oc = valid ? oe : (NN - 2);
    int i1 = oc / 100;
    int j1 = oc - i1 * 100;
    int qq = j1 >> 1;

    unsigned baseA;
    asm("{ .reg .u64 t; cvta.to.shared.u64 t, %1; cvt.u32.u64 %0, t; }"
        : "=r"(baseA) : "l"(smraw));
    unsigned tb = baseA - 400u * (unsigned)i1 - 4u * (unsigned)qq;

    unsigned aE0 = 0, aE1 = 0, aO0 = 0, aO1 = 0;
    int k = 0;
    int n8 = cnt & ~7;
    for (; k < n8; k += 8) {
        int4 ea = *(const int4*)(slist + k);
        int4 eb = *(const int4*)(slist + k + 4);
        unsigned w0, w1, w2, w3, w4, w5, w6, w7;
        asm("ld.shared.u32 %0,[%1];" : "=r"(w0) : "r"(tb + (unsigned)ea.x));
        asm("ld.shared.u32 %0,[%1];" : "=r"(w1) : "r"(tb + (unsigned)ea.y));
        asm("ld.shared.u32 %0,[%1];" : "=r"(w2) : "r"(tb + (unsigned)ea.z));
        asm("ld.shared.u32 %0,[%1];" : "=r"(w3) : "r"(tb + (unsigned)ea.w));
        asm("ld.shared.u32 %0,[%1];" : "=r"(w4) : "r"(tb + (unsigned)eb.x));
        asm("ld.shared.u32 %0,[%1];" : "=r"(w5) : "r"(tb + (unsigned)eb.y));
        asm("ld.shared.u32 %0,[%1];" : "=r"(w6) : "r"(tb + (unsigned)eb.z));
        asm("ld.shared.u32 %0,[%1];" : "=r"(w7) : "r"(tb + (unsigned)eb.w));
        aE0 = __dp2a_lo(w0, 0x0100u, aE0); aO0 = __dp2a_lo(w0, 0x0001u, aO0);
        aE1 = __dp2a_lo(w1, 0x0100u, aE1); aO1 = __dp2a_lo(w1, 0x0001u, aO1);
        aE0 = __dp2a_lo(w2, 0x0100u, aE0); aO0 = __dp2a_lo(w2, 0x0001u, aO0);
        aE1 = __dp2a_lo(w3, 0x0100u, aE1); aO1 = __dp2a_lo(w3, 0x0001u, aO1);
        aE0 = __dp2a_lo(w4, 0x0100u, aE0); aO0 = __dp2a_lo(w4, 0x0001u, aO0);
        aE1 = __dp2a_lo(w5, 0x0100u, aE1); aO1 = __dp2a_lo(w5, 0x0001u, aO1);
        aE0 = __dp2a_lo(w6, 0x0100u, aE0); aO0 = __dp2a_lo(w6, 0x0001u, aO0);
        aE1 = __dp2a_lo(w7, 0x0100u, aE1); aO1 = __dp2a_lo(w7, 0x0001u, aO1);
    }
    for (; k < cnt; ++k) {
        unsigned w0;
        asm("ld.shared.u32 %0,[%1];" : "=r"(w0) : "r"(tb + (unsigned)slist[k]));
        aE0 = __dp2a_lo(w0, 0x0100u, aE0);
        aO0 = __dp2a_lo(w0, 0x0001u, aO0);
    }
    float Te = __uint2float_rn(aE0 + aE1) * (float)(1.0 / QSCALE);
    float To = __uint2float_rn(aO0 + aO1) * (float)(1.0 / QSCALE);

    // slice partial of the (input-independent) rowsum S for both outputs
    int i2a = (100 * s) / NSLICE;
    int i2b = (100 * (s + 1)) / NSLICE;
    float sve = 0.f, svo = 0.f;
    const float2* A2 = (const float2*)c_tab.A;
    for (int i2 = i2a; i2 < i2b; ++i2) {
        int di = i1 - i2; if (di < 0) di = -di;
        float2 av = A2[di * 50 + qq];
        sve += av.x; svo += av.y;
    }

    if (valid) {
        *(float2*)&g_pT[s * 10240 + oe] = make_float2(Te, To);
        *(float2*)&g_pS[s * 10240 + oe] = make_float2(sve, svo);
    }

    // ---- last-of-chunk does the chunk reduce (5 blocks in parallel) ----
    __threadfence();
    __syncthreads();
    if (tid == 0) {
        int fin = atomicAdd(&g_dc[chunk], 1);
        lastFlag = (fin == NSLICE - 1);
    }
    __syncthreads();
    if (lastFlag) {
        __threadfence();                       // acquire all slice partials
        int widx = chunk * 1024 + tid;         // one float2 (2 outputs)
        float ls = 0.f;
        if (2 * widx < NN) {
            float Txe = 0.f, Txo = 0.f, Sxe = 0.f, Sxo = 0.f;
            #pragma unroll
            for (int q2 = 0; q2 < NSLICE; ++q2) {
                float2 t2 = ((const float2*)(g_pT + q2 * 10240))[widx];
                float2 s2 = ((const float2*)(g_pS + q2 * 10240))[widx];
                Txe += t2.x; Txo += t2.y;
                Sxe += s2.x; Sxo += s2.y;
            }
            float2 pr = ((const float2*)prob)[widx];
            float pxe = (pr.x >= 0.5f) ? 1.0f : 0.0f;
            float pxo = (pr.y >= 0.5f) ? 1.0f : 0.0f;
            ls = fabsf(pxe * Sxe - Txe) + fabsf(pxo * Sxo - Txo);
        }
        #pragma unroll
        for (int off = 16; off; off >>= 1)
            ls += __shfl_down_sync(0xffffffffu, ls, off);
        if (lane == 0) wsum[warp] = ls;
        __syncthreads();
        if (tid == 0) {
            float t = 0.f;
            #pragma unroll
            for (int w = 0; w < 32; ++w) t += wsum[w];
            g_cs[chunk] = t;
            __threadfence();
            int fin2 = atomicAdd(&g_done2, 1);
            if (fin2 == NCHUNK - 1) {          // final: all chunk scalars ready
                __threadfence();
                float tt = 0.f;
                #pragma unroll
                for (int c = 0; c < NCHUNK; ++c) tt += g_cs[c];
                out[0] = tt * (float)(1.0 / ((double)NN * (double)NN));
                // replay-safe counter reset (all atomics already happened)
                #pragma unroll
                for (int c = 0; c < NCHUNK; ++c) g_dc[c] = 0;
                g_done2 = 0;
                __threadfence();
            }
        }
    }
}

extern "C" void kernel_launch(void* const* d_in, const int* in_sizes, int n_in,
                              void* d_out, int out_size) {
    const float* prob = (const float*)d_in[0];
    const float* gt   = (const float*)d_in[1];
    float* out = (float*)d_out;

    cudaFuncSetAttribute(k_all, cudaFuncAttributeMaxDynamicSharedMemorySize, SMEM_BYTES);
    k_all<<<NB, NT, SMEM_BYTES>>>(prob, gt, out);
}